// round 1
// baseline (speedup 1.0000x reference)
#include <cuda_runtime.h>

// AbstractRelu (DeepPoly ReLU relaxation), elementwise over N fp32.
// out layout: [relu(x) (N)] [lb_slope*low (N)] [relu(high) (N)]
//
// Simplifications vs reference:
//   high_out = relu(high)   (crossing case algebraically collapses to `high`)
//   low_out  = (high<=0) ? 0 : (low<0 && low*low>high*high) ? 0 : low
//   x_out    = relu(x)

__global__ void __launch_bounds__(256, 8)
abstract_relu_kernel(const float4* __restrict__ x,
                     const float4* __restrict__ low,
                     const float4* __restrict__ high,
                     float4* __restrict__ x_out,
                     float4* __restrict__ low_out,
                     float4* __restrict__ high_out,
                     int n4)
{
    int i = blockIdx.x * blockDim.x + threadIdx.x;
    if (i >= n4) return;

    float4 xv = x[i];
    float4 lv = low[i];
    float4 hv = high[i];

    float4 xo, lo, ho;

    #define LANE(f)                                                        \
    {                                                                      \
        float xe = xv.f, le = lv.f, he = hv.f;                             \
        xo.f = fmaxf(xe, 0.0f);                                            \
        ho.f = fmaxf(he, 0.0f);                                            \
        float l = le;                                                      \
        /* inactive (h<=0): 0. crossing (l<0,h>0) with l^2>h^2: 0. else l */ \
        bool zero = (he <= 0.0f) || (le < 0.0f && le * le > he * he);      \
        lo.f = zero ? 0.0f : l;                                            \
    }

    LANE(x) LANE(y) LANE(z) LANE(w)
    #undef LANE

    x_out[i]    = xo;
    low_out[i]  = lo;
    high_out[i] = ho;
}

extern "C" void kernel_launch(void* const* d_in, const int* in_sizes, int n_in,
                              void* d_out, int out_size)
{
    const float* x    = (const float*)d_in[0];
    const float* low  = (const float*)d_in[1];
    const float* high = (const float*)d_in[2];
    float* out = (float*)d_out;

    const int n  = in_sizes[0];          // 16777216
    const int n4 = n / 4;                // divisible by 4

    float* x_out    = out;
    float* low_out  = out + n;
    float* high_out = out + 2 * (size_t)n;

    const int threads = 256;
    const int blocks  = (n4 + threads - 1) / threads;

    abstract_relu_kernel<<<blocks, threads>>>(
        (const float4*)x, (const float4*)low, (const float4*)high,
        (float4*)x_out, (float4*)low_out, (float4*)high_out, n4);
}